// round 11
// baseline (speedup 1.0000x reference)
#include <cuda_runtime.h>
#include <cuda_fp16.h>
#include <mma.h>

using namespace nvcuda;

#define BB   64
#define TT   512
#define KK   512
#define G3   1536
#define LDB  520
#define NTHREADS 384
#define SLD  20
#define TILE_F (16*SLD)
#define ABUF_LD 24

__device__ __half g_h_hi[2][2][BB * KK];
__device__ __half g_h_lo[2][2][BB * KK];
__device__ float  g_gi0[(size_t)TT * BB * G3];
__device__ unsigned int g_f0[2][32];   // L0 per-CTA completed-step flags [grp][cidx]
__device__ unsigned int g_f1[2][32];   // L1 per-CTA completed-step flags

__device__ __forceinline__ void load_weights(const float* __restrict__ W,
                                             __half* shi, __half* slo, int cidx) {
    for (int idx = threadIdx.x; idx < 48 * KK; idx += NTHREADS) {
        int row = idx >> 9, k = idx & 511;
        int grow = (row >> 4) * 512 + cidx * 16 + (row & 15);
        float v = W[(size_t)grow * KK + k];
        __half h = __float2half_rn(v);
        shi[row * LDB + k] = h;
        slo[row * LDB + k] = __float2half_rn(v - __half2float(h));
    }
}

typedef wmma::fragment<wmma::accumulator, 16, 16, 16, float> AccFrag;

// 3-pass fp16 GEMM, gates merged (proven version)
__device__ __forceinline__ void gemm3(const __half* Ahi, const __half* Alo,
                                      unsigned lda, const __half* Bhi,
                                      const __half* Blo, int k0, int k1,
                                      AccFrag acc[3]) {
    for (int kt = k0; kt < k1; ++kt) {
        wmma::fragment<wmma::matrix_a, 16, 16, 16, __half, wmma::row_major> ahi, alo;
        wmma::load_matrix_sync(ahi, Ahi + kt * 16, lda);
        wmma::load_matrix_sync(alo, Alo + kt * 16, lda);
#pragma unroll
        for (int gg = 0; gg < 3; gg++) {
            wmma::fragment<wmma::matrix_b, 16, 16, 16, __half, wmma::col_major> bh, bl;
            wmma::load_matrix_sync(bh, Bhi + gg * 16 * LDB + kt * 16, LDB);
            wmma::load_matrix_sync(bl, Blo + gg * 16 * LDB + kt * 16, LDB);
            wmma::mma_sync(acc[gg], ahi, bh, acc[gg]);
            wmma::mma_sync(acc[gg], alo, bh, acc[gg]);
            wmma::mma_sync(acc[gg], ahi, bl, acc[gg]);
        }
    }
}

__device__ __forceinline__ void reduce3(float* stage, int tilebase, int ks,
                                        AccFrag acc[3]) {
#pragma unroll
    for (int p = 0; p < 3; p++) {
        if (ks == p) {
#pragma unroll
            for (int gg = 0; gg < 3; gg++) {
                float* tp = stage + (tilebase + gg) * TILE_F;
                if (p > 0) {
                    AccFrag c;
                    wmma::load_matrix_sync(c, tp, SLD, wmma::mem_row_major);
                    for (int i = 0; i < c.num_elements; i++) acc[gg].x[i] += c.x[i];
                }
                wmma::store_matrix_sync(tp, acc[gg], SLD, wmma::mem_row_major);
            }
        }
        __syncthreads();
    }
}

// warp-parallel flag polls: lane i watches flag i, exit when all >= target
__device__ __forceinline__ void poll1(const unsigned int* f, unsigned ta, int lane) {
    volatile const unsigned int* p = f;
    for (;;) {
        unsigned v = p[lane];
        if (__all_sync(0xffffffffu, v >= ta)) break;
        __nanosleep(64);
    }
}
__device__ __forceinline__ void poll2(const unsigned int* fa, unsigned ta,
                                      const unsigned int* fb, unsigned tb, int lane) {
    volatile const unsigned int* pa = fa;
    volatile const unsigned int* pb = fb;
    for (;;) {
        unsigned va = pa[lane];
        unsigned vb = pb[lane];
        if (__all_sync(0xffffffffu, (va >= ta) && (vb >= tb))) break;
        __nanosleep(64);
    }
}
__device__ __forceinline__ void fence_gpu() {
    asm volatile("fence.acq_rel.gpu;" ::: "memory");
}

// ---------------- bulk: gi0 = x@W_ih0^T + b_ih0 + enc split + flag init ------
extern "C" __global__ void __launch_bounds__(NTHREADS, 1)
gru_bulk(const float* __restrict__ x, const float* __restrict__ enc,
         const float* __restrict__ Wih, const float* __restrict__ bih) {
    extern __shared__ __half smem[];
    __half* shi   = smem;
    __half* slo   = smem + 48 * LDB;
    float*  stage = (float*)(smem + 2 * 48 * LDB);
    __half* abuf  = (__half*)(stage + 12 * TILE_F);

    const int bid = blockIdx.x;
    const int cidx = bid & 31;
    const int tg   = bid >> 5;
    const int tid  = threadIdx.x, wid = tid >> 5, lane = tid & 31;
    const int rb = wid / 3, ks = wid % 3;
    const int k0 = ks * 11, k1 = (ks == 2) ? 32 : k0 + 11;

    {
        size_t i = (size_t)bid * NTHREADS + tid;
        size_t ne = (size_t)2 * BB * KK;
        if (i < ne) {
            int l = (int)(i / (BB * KK));
            int r = (int)(i % (BB * KK));
            float v = enc[i];
            __half hi = __float2half_rn(v);
            g_h_hi[l][1][r] = hi;
            g_h_lo[l][1][r] = __float2half_rn(v - __half2float(hi));
        }
        if (i < 64) {
            ((unsigned int*)g_f0)[i] = 0;
            ((unsigned int*)g_f1)[i] = 0;
        }
    }

    load_weights(Wih, shi, slo, cidx);
    __syncthreads();

    __half* myAhi = abuf + wid * 2 * 16 * ABUF_LD;
    __half* myAlo = myAhi + 16 * ABUF_LD;
    const int arow = lane >> 1;
    const int acol = (lane & 1) * 8;

    for (int tt = 0; tt < 32; tt++) {
        int t = tg * 32 + tt;
        AccFrag acc[3];
#pragma unroll
        for (int gg = 0; gg < 3; gg++) wmma::fill_fragment(acc[gg], 0.0f);

        const float* xrow = x + ((size_t)(rb * 16 + arow) * TT + t) * KK;
        for (int kt = k0; kt < k1; ++kt) {
            float4 v0 = *(const float4*)(xrow + kt * 16 + acol);
            float4 v1 = *(const float4*)(xrow + kt * 16 + acol + 4);
            float vv[8] = {v0.x, v0.y, v0.z, v0.w, v1.x, v1.y, v1.z, v1.w};
#pragma unroll
            for (int j = 0; j < 8; j++) {
                __half h = __float2half_rn(vv[j]);
                myAhi[arow * ABUF_LD + acol + j] = h;
                myAlo[arow * ABUF_LD + acol + j] = __float2half_rn(vv[j] - __half2float(h));
            }
            __syncwarp();
            wmma::fragment<wmma::matrix_a, 16, 16, 16, __half, wmma::row_major> ahi, alo;
            wmma::load_matrix_sync(ahi, myAhi, ABUF_LD);
            wmma::load_matrix_sync(alo, myAlo, ABUF_LD);
#pragma unroll
            for (int gg = 0; gg < 3; gg++) {
                wmma::fragment<wmma::matrix_b, 16, 16, 16, __half, wmma::col_major> bh, bl;
                wmma::load_matrix_sync(bh, shi + gg * 16 * LDB + kt * 16, LDB);
                wmma::load_matrix_sync(bl, slo + gg * 16 * LDB + kt * 16, LDB);
                wmma::mma_sync(acc[gg], ahi, bh, acc[gg]);
                wmma::mma_sync(acc[gg], alo, bh, acc[gg]);
                wmma::mma_sync(acc[gg], ahi, bl, acc[gg]);
            }
            __syncwarp();
        }
        reduce3(stage, rb * 3, ks, acc);
        for (int e = tid; e < 64 * 16; e += NTHREADS) {
            int row = e >> 4, c = e & 15, rb2 = row >> 4, rr = row & 15;
            int gc = cidx * 16 + c;
            const float* st = stage + rb2 * 3 * TILE_F;
            float* dst = &g_gi0[((size_t)t * BB + row) * G3];
            dst[gc]        = st[rr * SLD + c]              + bih[gc];
            dst[512 + gc]  = st[TILE_F + rr * SLD + c]     + bih[512 + gc];
            dst[1024 + gc] = st[2 * TILE_F + rr * SLD + c] + bih[1024 + gc];
        }
        __syncthreads();
    }
}

// ---------------- main: 64 L0 (6-way ksplit) + 64 L1; flag-based sync --------
extern "C" __global__ void __launch_bounds__(NTHREADS, 1)
gru_main(const float* __restrict__ Wih, const float* __restrict__ Whh,
         const float* __restrict__ bih, const float* __restrict__ bhh,
         float* __restrict__ out) {
    extern __shared__ __half smem[];
    const int bid = blockIdx.x, tid = threadIdx.x;
    const int wid = tid >> 5, lane = tid & 31;
    const bool L0 = (bid < 64);

    __half *sWih_hi = nullptr, *sWih_lo = nullptr, *sWhh_hi, *sWhh_lo;
    float* stage;
    int cidx, grp, b0;

    if (L0) {
        grp = bid >> 5; cidx = bid & 31; b0 = grp * 32;
        sWhh_hi = smem; sWhh_lo = smem + 48 * LDB;
        stage = (float*)(smem + 2 * 48 * LDB);        // 36 tiles
        load_weights(Whh, sWhh_hi, sWhh_lo, cidx);
    } else {
        int r = bid - 64;
        grp = r >> 5; cidx = r & 31; b0 = grp * 32;
        sWih_hi = smem;                sWih_lo = smem + 48 * LDB;
        sWhh_hi = smem + 2 * 48 * LDB; sWhh_lo = smem + 3 * 48 * LDB;
        stage = (float*)(smem + 4 * 48 * LDB);        // 12 tiles
        load_weights(Wih + (size_t)G3 * KK, sWih_hi, sWih_lo, cidx);
        load_weights(Whh + (size_t)G3 * KK, sWhh_hi, sWhh_lo, cidx);
    }
    __syncthreads();

    int srcid, rb, ks, k0, k1;
    if (L0) {
        srcid = 1; rb = wid / 6; ks = wid % 6;
        k0 = (ks < 2) ? ks * 6 : 12 + (ks - 2) * 5;
        k1 = k0 + ((ks < 2) ? 6 : 5);
    } else {
        srcid = wid / 6; rb = (wid % 6) / 3; ks = wid % 3;
        k0 = ks * 11; k1 = (ks == 2) ? 32 : k0 + 11;
    }
    const int tilebase = L0 ? 0 : ((srcid * 2 + rb) * 3);
    const int layer = L0 ? 0 : 1;
    const float* bihL = bih + layer * G3;
    const float* bhhL = bhh + layer * G3;

    // ---- epilogue caches: biases + exact h_prev in registers ----
    float cbiR[2], cbiZ[2], cbiN[2], cbhR[2], cbhZ[2], cbhN[2], hp_reg[2];
    int nelem = 0;
#pragma unroll
    for (int q = 0; q < 2; q++) {
        int e = tid + q * NTHREADS;
        if (e >= 32 * 16) break;
        int row = e >> 4, c = e & 15;
        int gc = cidx * 16 + c;
        int hidx = (b0 + row) * KK + gc;
        cbiR[q] = L0 ? 0.f : bihL[gc];
        cbiZ[q] = L0 ? 0.f : bihL[512 + gc];
        cbiN[q] = L0 ? 0.f : bihL[1024 + gc];
        cbhR[q] = bhhL[gc];
        cbhZ[q] = bhhL[512 + gc];
        cbhN[q] = bhhL[1024 + gc];
        hp_reg[q] = __half2float(g_h_hi[layer][1][hidx]) +
                    __half2float(g_h_lo[layer][1][hidx]);
        nelem++;
    }

    for (int t = 0; t < TT; t++) {
        // gi0 prefetch (L0): immutable, overlaps wait + GEMM
        float pgi[6];
        if (L0) {
#pragma unroll
            for (int q = 0; q < 2; q++) {
                int e = tid + q * NTHREADS;
                if (e >= 32 * 16) break;
                int row = e >> 4, c = e & 15;
                const float* gi = &g_gi0[((size_t)t * BB + b0 + row) * G3] + cidx * 16 + c;
                pgi[q * 3 + 0] = gi[0];
                pgi[q * 3 + 1] = gi[512];
                pgi[q * 3 + 2] = gi[1024];
            }
        }

        // ---- warp-parallel flag waits (own group only) ----
        if (L0) {
            poll2(&g_f0[grp][0], (unsigned)t,
                  &g_f1[grp][0], (unsigned)(t >= 1 ? t - 1 : 0), lane);
        } else if (srcid == 0) {
            poll1(&g_f0[grp][0], (unsigned)(t + 1), lane);   // need h0(t)
        } else {
            poll1(&g_f1[grp][0], (unsigned)t, lane);         // need h1(t-1)
        }
        if (lane == 0) fence_gpu();
        __syncwarp();

        const __half *Ahi, *Alo;
        if (L0) {
            int pv = (t + 1) & 1;
            Ahi = &g_h_hi[0][pv][b0 * KK] + rb * 16 * KK;
            Alo = &g_h_lo[0][pv][b0 * KK] + rb * 16 * KK;
        } else if (srcid == 0) {
            int p = t & 1;
            Ahi = &g_h_hi[0][p][b0 * KK] + rb * 16 * KK;
            Alo = &g_h_lo[0][p][b0 * KK] + rb * 16 * KK;
        } else {
            int pv = (t + 1) & 1;
            Ahi = &g_h_hi[1][pv][b0 * KK] + rb * 16 * KK;
            Alo = &g_h_lo[1][pv][b0 * KK] + rb * 16 * KK;
        }
        const __half* Bh = (srcid == 0) ? sWih_hi : sWhh_hi;
        const __half* Bl = (srcid == 0) ? sWih_lo : sWhh_lo;

        AccFrag acc[3];
#pragma unroll
        for (int gg = 0; gg < 3; gg++) wmma::fill_fragment(acc[gg], 0.0f);
        gemm3(Ahi, Alo, KK, Bh, Bl, k0, k1, acc);

        if (L0) {
#pragma unroll
            for (int gg = 0; gg < 3; gg++)
                wmma::store_matrix_sync(stage + (wid * 3 + gg) * TILE_F, acc[gg],
                                        SLD, wmma::mem_row_major);
            __syncthreads();
        } else {
            reduce3(stage, tilebase, ks, acc);
        }

#pragma unroll
        for (int q = 0; q < 2; q++) {
            if (q >= nelem) break;
            int e = tid + q * NTHREADS;
            int row = e >> 4, c = e & 15, rb2 = row >> 4, rr = row & 15;
            int gc = cidx * 16 + c;
            float giR, giZ, giN, ghR, ghZ, ghN;
            if (L0) {
                giR = pgi[q * 3 + 0]; giZ = pgi[q * 3 + 1]; giN = pgi[q * 3 + 2];
                ghR = 0.f; ghZ = 0.f; ghN = 0.f;
                const int off = rr * SLD + c;
#pragma unroll
                for (int s = 0; s < 6; s++) {
                    const float* tp = stage + ((rb2 * 6 + s) * 3) * TILE_F + off;
                    ghR += tp[0];
                    ghZ += tp[TILE_F];
                    ghN += tp[2 * TILE_F];
                }
            } else {
                const float* sg = stage + rb2 * 3 * TILE_F;
                const float* sh = stage + (2 + rb2) * 3 * TILE_F;
                giR = sg[rr * SLD + c]              + cbiR[q];
                giZ = sg[TILE_F + rr * SLD + c]     + cbiZ[q];
                giN = sg[2 * TILE_F + rr * SLD + c] + cbiN[q];
                ghR = sh[rr * SLD + c];
                ghZ = sh[TILE_F + rr * SLD + c];
                ghN = sh[2 * TILE_F + rr * SLD + c];
            }
            float r = 1.0f / (1.0f + expf(-(giR + ghR + cbhR[q])));
            float z = 1.0f / (1.0f + expf(-(giZ + ghZ + cbhZ[q])));
            float n = tanhf(giN + r * (ghN + cbhN[q]));

            int hidx = (b0 + row) * KK + gc;
            float hn = (1.0f - z) * n + z * hp_reg[q];
            hp_reg[q] = hn;

            int pc = t & 1;
            __half hh = __float2half_rn(hn);
            g_h_hi[layer][pc][hidx] = hh;
            g_h_lo[layer][pc][hidx] = __float2half_rn(hn - __half2float(hh));

            if (!L0)
                out[((size_t)(b0 + row) * TT + t) * KK + gc] = hn;
            if (t == TT - 1)
                out[(size_t)BB * TT * KK + (size_t)layer * BB * KK + hidx] = hn;
        }
        // ---- publish: barrier, then one fence + one plain flag store --------
        __syncthreads();
        if (tid == 0) {
            fence_gpu();
            if (L0) *(volatile unsigned int*)&g_f0[grp][cidx] = (unsigned)(t + 1);
            else    *(volatile unsigned int*)&g_f1[grp][cidx] = (unsigned)(t + 1);
        }
    }
}

extern "C" void kernel_launch(void* const* d_in, const int* in_sizes, int n_in,
                              void* d_out, int out_size) {
    const float* x   = (const float*)d_in[0];
    const float* enc = (const float*)d_in[1];
    const float* Wih = (const float*)d_in[2];
    const float* Whh = (const float*)d_in[3];
    const float* bih = (const float*)d_in[4];
    const float* bhh = (const float*)d_in[5];
    float* out = (float*)d_out;
    (void)in_sizes; (void)n_in; (void)out_size;

    size_t smem_main = (size_t)4 * 48 * LDB * 2 + (size_t)12 * TILE_F * 4;
    size_t smem_bulk = (size_t)2 * 48 * LDB * 2 + (size_t)12 * TILE_F * 4
                     + (size_t)12 * 2 * 16 * ABUF_LD * 2;
    cudaFuncSetAttribute(gru_main, cudaFuncAttributeMaxDynamicSharedMemorySize,
                         (int)smem_main);
    cudaFuncSetAttribute(gru_bulk, cudaFuncAttributeMaxDynamicSharedMemorySize,
                         (int)smem_bulk);

    gru_bulk<<<512, NTHREADS, smem_bulk>>>(x, enc, Wih, bih);
    gru_main<<<128, NTHREADS, smem_main>>>(Wih, Whh, bih, bhh, out);
}

// round 12
// speedup vs baseline: 1.7607x; 1.7607x over previous
#include <cuda_runtime.h>
#include <cuda_fp16.h>
#include <mma.h>

using namespace nvcuda;

#define BB   64
#define TT   512
#define KK   512
#define G3   1536
#define LDB  520
#define NTHREADS 384
#define SLD  20
#define TILE_F (16*SLD)
#define ABUF_LD 24

__device__ __half g_h_hi[2][2][BB * KK];
__device__ __half g_h_lo[2][2][BB * KK];
__device__ float  g_gi0[(size_t)TT * BB * G3];
// group-local step counters, one 128B line each
__device__ __align__(128) unsigned int g_c0g[2][32];
__device__ __align__(128) unsigned int g_c1g[2][32];

__device__ __forceinline__ void load_weights(const float* __restrict__ W,
                                             __half* shi, __half* slo, int cidx) {
    for (int idx = threadIdx.x; idx < 48 * KK; idx += NTHREADS) {
        int row = idx >> 9, k = idx & 511;
        int grow = (row >> 4) * 512 + cidx * 16 + (row & 15);
        float v = W[(size_t)grow * KK + k];
        __half h = __float2half_rn(v);
        shi[row * LDB + k] = h;
        slo[row * LDB + k] = __float2half_rn(v - __half2float(h));
    }
}

typedef wmma::fragment<wmma::accumulator, 16, 16, 16, float> AccFrag;

// 3-pass fp16 GEMM, gates merged (proven version)
__device__ __forceinline__ void gemm3(const __half* Ahi, const __half* Alo,
                                      unsigned lda, const __half* Bhi,
                                      const __half* Blo, int k0, int k1,
                                      AccFrag acc[3]) {
    for (int kt = k0; kt < k1; ++kt) {
        wmma::fragment<wmma::matrix_a, 16, 16, 16, __half, wmma::row_major> ahi, alo;
        wmma::load_matrix_sync(ahi, Ahi + kt * 16, lda);
        wmma::load_matrix_sync(alo, Alo + kt * 16, lda);
#pragma unroll
        for (int gg = 0; gg < 3; gg++) {
            wmma::fragment<wmma::matrix_b, 16, 16, 16, __half, wmma::col_major> bh, bl;
            wmma::load_matrix_sync(bh, Bhi + gg * 16 * LDB + kt * 16, LDB);
            wmma::load_matrix_sync(bl, Blo + gg * 16 * LDB + kt * 16, LDB);
            wmma::mma_sync(acc[gg], ahi, bh, acc[gg]);
            wmma::mma_sync(acc[gg], alo, bh, acc[gg]);
            wmma::mma_sync(acc[gg], ahi, bl, acc[gg]);
        }
    }
}

__device__ __forceinline__ void reduce3(float* stage, int tilebase, int ks,
                                        AccFrag acc[3]) {
#pragma unroll
    for (int p = 0; p < 3; p++) {
        if (ks == p) {
#pragma unroll
            for (int gg = 0; gg < 3; gg++) {
                float* tp = stage + (tilebase + gg) * TILE_F;
                if (p > 0) {
                    AccFrag c;
                    wmma::load_matrix_sync(c, tp, SLD, wmma::mem_row_major);
                    for (int i = 0; i < c.num_elements; i++) acc[gg].x[i] += c.x[i];
                }
                wmma::store_matrix_sync(tp, acc[gg], SLD, wmma::mem_row_major);
            }
        }
        __syncthreads();
    }
}

__device__ __forceinline__ void spin_ge(volatile unsigned int* p, unsigned tgt) {
    while (*p < tgt) { __nanosleep(64); }
}
__device__ __forceinline__ void fence_gpu() {
    asm volatile("fence.acq_rel.gpu;" ::: "memory");
}

// ---------------- bulk: gi0 = x@W_ih0^T + b_ih0 + enc split + counter init ---
extern "C" __global__ void __launch_bounds__(NTHREADS, 1)
gru_bulk(const float* __restrict__ x, const float* __restrict__ enc,
         const float* __restrict__ Wih, const float* __restrict__ bih) {
    extern __shared__ __half smem[];
    __half* shi   = smem;
    __half* slo   = smem + 48 * LDB;
    float*  stage = (float*)(smem + 2 * 48 * LDB);
    __half* abuf  = (__half*)(stage + 12 * TILE_F);

    const int bid = blockIdx.x;
    const int cidx = bid & 31;
    const int tg   = bid >> 5;
    const int tid  = threadIdx.x, wid = tid >> 5, lane = tid & 31;
    const int rb = wid / 3, ks = wid % 3;
    const int k0 = ks * 11, k1 = (ks == 2) ? 32 : k0 + 11;

    {
        size_t i = (size_t)bid * NTHREADS + tid;
        size_t ne = (size_t)2 * BB * KK;
        if (i < ne) {
            int l = (int)(i / (BB * KK));
            int r = (int)(i % (BB * KK));
            float v = enc[i];
            __half hi = __float2half_rn(v);
            g_h_hi[l][1][r] = hi;
            g_h_lo[l][1][r] = __float2half_rn(v - __half2float(hi));
        }
        if (i == 0) {
            g_c0g[0][0] = 0; g_c0g[1][0] = 0;
            g_c1g[0][0] = 0; g_c1g[1][0] = 0;
        }
    }

    load_weights(Wih, shi, slo, cidx);
    __syncthreads();

    __half* myAhi = abuf + wid * 2 * 16 * ABUF_LD;
    __half* myAlo = myAhi + 16 * ABUF_LD;
    const int arow = lane >> 1;
    const int acol = (lane & 1) * 8;

    for (int tt = 0; tt < 32; tt++) {
        int t = tg * 32 + tt;
        AccFrag acc[3];
#pragma unroll
        for (int gg = 0; gg < 3; gg++) wmma::fill_fragment(acc[gg], 0.0f);

        const float* xrow = x + ((size_t)(rb * 16 + arow) * TT + t) * KK;
        for (int kt = k0; kt < k1; ++kt) {
            float4 v0 = *(const float4*)(xrow + kt * 16 + acol);
            float4 v1 = *(const float4*)(xrow + kt * 16 + acol + 4);
            float vv[8] = {v0.x, v0.y, v0.z, v0.w, v1.x, v1.y, v1.z, v1.w};
#pragma unroll
            for (int j = 0; j < 8; j++) {
                __half h = __float2half_rn(vv[j]);
                myAhi[arow * ABUF_LD + acol + j] = h;
                myAlo[arow * ABUF_LD + acol + j] = __float2half_rn(vv[j] - __half2float(h));
            }
            __syncwarp();
            wmma::fragment<wmma::matrix_a, 16, 16, 16, __half, wmma::row_major> ahi, alo;
            wmma::load_matrix_sync(ahi, myAhi, ABUF_LD);
            wmma::load_matrix_sync(alo, myAlo, ABUF_LD);
#pragma unroll
            for (int gg = 0; gg < 3; gg++) {
                wmma::fragment<wmma::matrix_b, 16, 16, 16, __half, wmma::col_major> bh, bl;
                wmma::load_matrix_sync(bh, shi + gg * 16 * LDB + kt * 16, LDB);
                wmma::load_matrix_sync(bl, slo + gg * 16 * LDB + kt * 16, LDB);
                wmma::mma_sync(acc[gg], ahi, bh, acc[gg]);
                wmma::mma_sync(acc[gg], alo, bh, acc[gg]);
                wmma::mma_sync(acc[gg], ahi, bl, acc[gg]);
            }
            __syncwarp();
        }
        reduce3(stage, rb * 3, ks, acc);
        for (int e = tid; e < 64 * 16; e += NTHREADS) {
            int row = e >> 4, c = e & 15, rb2 = row >> 4, rr = row & 15;
            int gc = cidx * 16 + c;
            const float* st = stage + rb2 * 3 * TILE_F;
            float* dst = &g_gi0[((size_t)t * BB + row) * G3];
            dst[gc]        = st[rr * SLD + c]              + bih[gc];
            dst[512 + gc]  = st[TILE_F + rr * SLD + c]     + bih[512 + gc];
            dst[1024 + gc] = st[2 * TILE_F + rr * SLD + c] + bih[1024 + gc];
        }
        __syncthreads();
    }
}

// ---------------- main: 64 L0 (6-way ksplit) + 64 L1; group-local counters ---
extern "C" __global__ void __launch_bounds__(NTHREADS, 1)
gru_main(const float* __restrict__ Wih, const float* __restrict__ Whh,
         const float* __restrict__ bih, const float* __restrict__ bhh,
         float* __restrict__ out) {
    extern __shared__ __half smem[];
    const int bid = blockIdx.x, tid = threadIdx.x;
    const int wid = tid >> 5, lane = tid & 31;
    const bool L0 = (bid < 64);

    __half *sWih_hi = nullptr, *sWih_lo = nullptr, *sWhh_hi, *sWhh_lo;
    float* stage;
    int cidx, grp, b0;

    if (L0) {
        grp = bid >> 5; cidx = bid & 31; b0 = grp * 32;
        sWhh_hi = smem; sWhh_lo = smem + 48 * LDB;
        stage = (float*)(smem + 2 * 48 * LDB);        // 36 tiles
        load_weights(Whh, sWhh_hi, sWhh_lo, cidx);
    } else {
        int r = bid - 64;
        grp = r >> 5; cidx = r & 31; b0 = grp * 32;
        sWih_hi = smem;                sWih_lo = smem + 48 * LDB;
        sWhh_hi = smem + 2 * 48 * LDB; sWhh_lo = smem + 3 * 48 * LDB;
        stage = (float*)(smem + 4 * 48 * LDB);        // 12 tiles
        load_weights(Wih + (size_t)G3 * KK, sWih_hi, sWih_lo, cidx);
        load_weights(Whh + (size_t)G3 * KK, sWhh_hi, sWhh_lo, cidx);
    }
    __syncthreads();

    int srcid, rb, ks, k0, k1;
    if (L0) {
        srcid = 1; rb = wid / 6; ks = wid % 6;
        k0 = (ks < 2) ? ks * 6 : 12 + (ks - 2) * 5;
        k1 = k0 + ((ks < 2) ? 6 : 5);
    } else {
        srcid = wid / 6; rb = (wid % 6) / 3; ks = wid % 3;
        k0 = ks * 11; k1 = (ks == 2) ? 32 : k0 + 11;
    }
    const int tilebase = L0 ? 0 : ((srcid * 2 + rb) * 3);
    const int layer = L0 ? 0 : 1;
    const float* bihL = bih + layer * G3;
    const float* bhhL = bhh + layer * G3;

    // ---- epilogue caches: biases + exact h_prev in registers ----
    float cbiR[2], cbiZ[2], cbiN[2], cbhR[2], cbhZ[2], cbhN[2], hp_reg[2];
    int nelem = 0;
#pragma unroll
    for (int q = 0; q < 2; q++) {
        int e = tid + q * NTHREADS;
        if (e >= 32 * 16) break;
        int row = e >> 4, c = e & 15;
        int gc = cidx * 16 + c;
        int hidx = (b0 + row) * KK + gc;
        cbiR[q] = L0 ? 0.f : bihL[gc];
        cbiZ[q] = L0 ? 0.f : bihL[512 + gc];
        cbiN[q] = L0 ? 0.f : bihL[1024 + gc];
        cbhR[q] = bhhL[gc];
        cbhZ[q] = bhhL[512 + gc];
        cbhN[q] = bhhL[1024 + gc];
        hp_reg[q] = __half2float(g_h_hi[layer][1][hidx]) +
                    __half2float(g_h_lo[layer][1][hidx]);
        nelem++;
    }

    for (int t = 0; t < TT; t++) {
        // gi0 prefetch (L0): immutable, overlaps wait + GEMM
        float pgi[6];
        if (L0) {
#pragma unroll
            for (int q = 0; q < 2; q++) {
                int e = tid + q * NTHREADS;
                if (e >= 32 * 16) break;
                int row = e >> 4, c = e & 15;
                const float* gi = &g_gi0[((size_t)t * BB + b0 + row) * G3] + cidx * 16 + c;
                pgi[q * 3 + 0] = gi[0];
                pgi[q * 3 + 1] = gi[512];
                pgi[q * 3 + 2] = gi[1024];
            }
        }

        // ---- r10 spin structure, group-local counters ----
        if (lane == 0) {
            if (L0) {
                spin_ge(&g_c0g[grp][0], (unsigned)(32 * t));
                if (t >= 1) spin_ge(&g_c1g[grp][0], (unsigned)(32 * (t - 1)));
            } else if (srcid == 0) {
                spin_ge(&g_c0g[grp][0], (unsigned)(32 * (t + 1)));  // need h0(t)
            } else {
                spin_ge(&g_c1g[grp][0], (unsigned)(32 * t));        // need h1(t-1)
            }
            fence_gpu();
        }
        __syncwarp();

        const __half *Ahi, *Alo;
        if (L0) {
            int pv = (t + 1) & 1;
            Ahi = &g_h_hi[0][pv][b0 * KK] + rb * 16 * KK;
            Alo = &g_h_lo[0][pv][b0 * KK] + rb * 16 * KK;
        } else if (srcid == 0) {
            int p = t & 1;
            Ahi = &g_h_hi[0][p][b0 * KK] + rb * 16 * KK;
            Alo = &g_h_lo[0][p][b0 * KK] + rb * 16 * KK;
        } else {
            int pv = (t + 1) & 1;
            Ahi = &g_h_hi[1][pv][b0 * KK] + rb * 16 * KK;
            Alo = &g_h_lo[1][pv][b0 * KK] + rb * 16 * KK;
        }
        const __half* Bh = (srcid == 0) ? sWih_hi : sWhh_hi;
        const __half* Bl = (srcid == 0) ? sWih_lo : sWhh_lo;

        AccFrag acc[3];
#pragma unroll
        for (int gg = 0; gg < 3; gg++) wmma::fill_fragment(acc[gg], 0.0f);
        gemm3(Ahi, Alo, KK, Bh, Bl, k0, k1, acc);

        if (L0) {
#pragma unroll
            for (int gg = 0; gg < 3; gg++)
                wmma::store_matrix_sync(stage + (wid * 3 + gg) * TILE_F, acc[gg],
                                        SLD, wmma::mem_row_major);
            __syncthreads();
        } else {
            reduce3(stage, tilebase, ks, acc);
        }

#pragma unroll
        for (int q = 0; q < 2; q++) {
            if (q >= nelem) break;
            int e = tid + q * NTHREADS;
            int row = e >> 4, c = e & 15, rb2 = row >> 4, rr = row & 15;
            int gc = cidx * 16 + c;
            float giR, giZ, giN, ghR, ghZ, ghN;
            if (L0) {
                giR = pgi[q * 3 + 0]; giZ = pgi[q * 3 + 1]; giN = pgi[q * 3 + 2];
                ghR = 0.f; ghZ = 0.f; ghN = 0.f;
                const int off = rr * SLD + c;
#pragma unroll
                for (int s = 0; s < 6; s++) {
                    const float* tp = stage + ((rb2 * 6 + s) * 3) * TILE_F + off;
                    ghR += tp[0];
                    ghZ += tp[TILE_F];
                    ghN += tp[2 * TILE_F];
                }
            } else {
                const float* sg = stage + rb2 * 3 * TILE_F;
                const float* sh = stage + (2 + rb2) * 3 * TILE_F;
                giR = sg[rr * SLD + c]              + cbiR[q];
                giZ = sg[TILE_F + rr * SLD + c]     + cbiZ[q];
                giN = sg[2 * TILE_F + rr * SLD + c] + cbiN[q];
                ghR = sh[rr * SLD + c];
                ghZ = sh[TILE_F + rr * SLD + c];
                ghN = sh[2 * TILE_F + rr * SLD + c];
            }
            float r = 1.0f / (1.0f + expf(-(giR + ghR + cbhR[q])));
            float z = 1.0f / (1.0f + expf(-(giZ + ghZ + cbhZ[q])));
            float n = tanhf(giN + r * (ghN + cbhN[q]));

            int hidx = (b0 + row) * KK + gc;
            float hn = (1.0f - z) * n + z * hp_reg[q];
            hp_reg[q] = hn;

            int pc = t & 1;
            __half hh = __float2half_rn(hn);
            g_h_hi[layer][pc][hidx] = hh;
            g_h_lo[layer][pc][hidx] = __float2half_rn(hn - __half2float(hh));

            if (!L0)
                out[((size_t)(b0 + row) * TT + t) * KK + gc] = hn;
            if (t == TT - 1)
                out[(size_t)BB * TT * KK + (size_t)layer * BB * KK + hidx] = hn;
        }
        __syncthreads();
        if (tid == 0) {
            fence_gpu();
            if (L0) atomicAdd(&g_c0g[grp][0], 1u);
            else    atomicAdd(&g_c1g[grp][0], 1u);
        }
    }
}

extern "C" void kernel_launch(void* const* d_in, const int* in_sizes, int n_in,
                              void* d_out, int out_size) {
    const float* x   = (const float*)d_in[0];
    const float* enc = (const float*)d_in[1];
    const float* Wih = (const float*)d_in[2];
    const float* Whh = (const float*)d_in[3];
    const float* bih = (const float*)d_in[4];
    const float* bhh = (const float*)d_in[5];
    float* out = (float*)d_out;
    (void)in_sizes; (void)n_in; (void)out_size;

    size_t smem_main = (size_t)4 * 48 * LDB * 2 + (size_t)12 * TILE_F * 4;
    size_t smem_bulk = (size_t)2 * 48 * LDB * 2 + (size_t)12 * TILE_F * 4
                     + (size_t)12 * 2 * 16 * ABUF_LD * 2;
    cudaFuncSetAttribute(gru_main, cudaFuncAttributeMaxDynamicSharedMemorySize,
                         (int)smem_main);
    cudaFuncSetAttribute(gru_bulk, cudaFuncAttributeMaxDynamicSharedMemorySize,
                         (int)smem_bulk);

    gru_bulk<<<512, NTHREADS, smem_bulk>>>(x, enc, Wih, bih);
    gru_main<<<128, NTHREADS, smem_main>>>(Wih, Whh, bih, bhh, out);
}

// round 13
// speedup vs baseline: 1.8390x; 1.0444x over previous
#include <cuda_runtime.h>
#include <cuda_fp16.h>
#include <mma.h>

using namespace nvcuda;

#define BB   64
#define TT   512
#define KK   512
#define G3   1536
#define LDB  520
#define NTHREADS 384
#define SLD  20
#define TILE_F (16*SLD)
#define ABUF_LD 24

__device__ __half g_h_hi[2][2][BB * KK];
__device__ __half g_h_lo[2][2][BB * KK];
__device__ float  g_gi0[(size_t)TT * BB * G3];
// group-local step counters, one 128B line each
__device__ __align__(128) unsigned int g_c0g[2][32];
__device__ __align__(128) unsigned int g_c1g[2][32];

__device__ __forceinline__ void load_weights(const float* __restrict__ W,
                                             __half* shi, __half* slo, int cidx) {
    for (int idx = threadIdx.x; idx < 48 * KK; idx += NTHREADS) {
        int row = idx >> 9, k = idx & 511;
        int grow = (row >> 4) * 512 + cidx * 16 + (row & 15);
        float v = W[(size_t)grow * KK + k];
        __half h = __float2half_rn(v);
        shi[row * LDB + k] = h;
        slo[row * LDB + k] = __float2half_rn(v - __half2float(h));
    }
}

typedef wmma::fragment<wmma::accumulator, 16, 16, 16, float> AccFrag;

// 3-pass fp16 GEMM body with COMPILE-TIME trip count so ptxas can unroll and
// overlap the independent per-tile A loads (MLP>1 instead of 1).
template<int NT>
__device__ __forceinline__ void gemm3_fix(const __half* Ahi, const __half* Alo,
                                          unsigned lda, const __half* Bhi,
                                          const __half* Blo, int k0,
                                          AccFrag acc[3]) {
#pragma unroll
    for (int i = 0; i < NT; ++i) {
        const int kt = k0 + i;
        wmma::fragment<wmma::matrix_a, 16, 16, 16, __half, wmma::row_major> ahi, alo;
        wmma::load_matrix_sync(ahi, Ahi + kt * 16, lda);
        wmma::load_matrix_sync(alo, Alo + kt * 16, lda);
#pragma unroll
        for (int gg = 0; gg < 3; gg++) {
            wmma::fragment<wmma::matrix_b, 16, 16, 16, __half, wmma::col_major> bh, bl;
            wmma::load_matrix_sync(bh, Bhi + gg * 16 * LDB + kt * 16, LDB);
            wmma::load_matrix_sync(bl, Blo + gg * 16 * LDB + kt * 16, LDB);
            wmma::mma_sync(acc[gg], ahi, bh, acc[gg]);
            wmma::mma_sync(acc[gg], alo, bh, acc[gg]);
            wmma::mma_sync(acc[gg], ahi, bl, acc[gg]);
        }
    }
}

// dispatch on the 4 trip counts that occur: {5,6} (L0), {10,11} (L1/bulk)
__device__ __forceinline__ void gemm3(const __half* Ahi, const __half* Alo,
                                      unsigned lda, const __half* Bhi,
                                      const __half* Blo, int k0, int k1,
                                      AccFrag acc[3]) {
    const int nt = k1 - k0;
    if (nt == 5)       gemm3_fix<5>(Ahi, Alo, lda, Bhi, Blo, k0, acc);
    else if (nt == 6)  gemm3_fix<6>(Ahi, Alo, lda, Bhi, Blo, k0, acc);
    else if (nt == 10) gemm3_fix<10>(Ahi, Alo, lda, Bhi, Blo, k0, acc);
    else               gemm3_fix<11>(Ahi, Alo, lda, Bhi, Blo, k0, acc);
}

__device__ __forceinline__ void reduce3(float* stage, int tilebase, int ks,
                                        AccFrag acc[3]) {
#pragma unroll
    for (int p = 0; p < 3; p++) {
        if (ks == p) {
#pragma unroll
            for (int gg = 0; gg < 3; gg++) {
                float* tp = stage + (tilebase + gg) * TILE_F;
                if (p > 0) {
                    AccFrag c;
                    wmma::load_matrix_sync(c, tp, SLD, wmma::mem_row_major);
                    for (int i = 0; i < c.num_elements; i++) acc[gg].x[i] += c.x[i];
                }
                wmma::store_matrix_sync(tp, acc[gg], SLD, wmma::mem_row_major);
            }
        }
        __syncthreads();
    }
}

__device__ __forceinline__ void spin_ge(volatile unsigned int* p, unsigned tgt) {
    while (*p < tgt) { __nanosleep(64); }
}
__device__ __forceinline__ void fence_gpu() {
    asm volatile("fence.acq_rel.gpu;" ::: "memory");
}

// ---------------- bulk: gi0 = x@W_ih0^T + b_ih0 + enc split + counter init ---
extern "C" __global__ void __launch_bounds__(NTHREADS, 1)
gru_bulk(const float* __restrict__ x, const float* __restrict__ enc,
         const float* __restrict__ Wih, const float* __restrict__ bih) {
    extern __shared__ __half smem[];
    __half* shi   = smem;
    __half* slo   = smem + 48 * LDB;
    float*  stage = (float*)(smem + 2 * 48 * LDB);
    __half* abuf  = (__half*)(stage + 12 * TILE_F);

    const int bid = blockIdx.x;
    const int cidx = bid & 31;
    const int tg   = bid >> 5;
    const int tid  = threadIdx.x, wid = tid >> 5, lane = tid & 31;
    const int rb = wid / 3, ks = wid % 3;
    const int k0 = ks * 11, k1 = (ks == 2) ? 32 : k0 + 11;

    {
        size_t i = (size_t)bid * NTHREADS + tid;
        size_t ne = (size_t)2 * BB * KK;
        if (i < ne) {
            int l = (int)(i / (BB * KK));
            int r = (int)(i % (BB * KK));
            float v = enc[i];
            __half hi = __float2half_rn(v);
            g_h_hi[l][1][r] = hi;
            g_h_lo[l][1][r] = __float2half_rn(v - __half2float(hi));
        }
        if (i == 0) {
            g_c0g[0][0] = 0; g_c0g[1][0] = 0;
            g_c1g[0][0] = 0; g_c1g[1][0] = 0;
        }
    }

    load_weights(Wih, shi, slo, cidx);
    __syncthreads();

    __half* myAhi = abuf + wid * 2 * 16 * ABUF_LD;
    __half* myAlo = myAhi + 16 * ABUF_LD;
    const int arow = lane >> 1;
    const int acol = (lane & 1) * 8;

    for (int tt = 0; tt < 32; tt++) {
        int t = tg * 32 + tt;
        AccFrag acc[3];
#pragma unroll
        for (int gg = 0; gg < 3; gg++) wmma::fill_fragment(acc[gg], 0.0f);

        const float* xrow = x + ((size_t)(rb * 16 + arow) * TT + t) * KK;
        for (int kt = k0; kt < k1; ++kt) {
            float4 v0 = *(const float4*)(xrow + kt * 16 + acol);
            float4 v1 = *(const float4*)(xrow + kt * 16 + acol + 4);
            float vv[8] = {v0.x, v0.y, v0.z, v0.w, v1.x, v1.y, v1.z, v1.w};
#pragma unroll
            for (int j = 0; j < 8; j++) {
                __half h = __float2half_rn(vv[j]);
                myAhi[arow * ABUF_LD + acol + j] = h;
                myAlo[arow * ABUF_LD + acol + j] = __float2half_rn(vv[j] - __half2float(h));
            }
            __syncwarp();
            wmma::fragment<wmma::matrix_a, 16, 16, 16, __half, wmma::row_major> ahi, alo;
            wmma::load_matrix_sync(ahi, myAhi, ABUF_LD);
            wmma::load_matrix_sync(alo, myAlo, ABUF_LD);
#pragma unroll
            for (int gg = 0; gg < 3; gg++) {
                wmma::fragment<wmma::matrix_b, 16, 16, 16, __half, wmma::col_major> bh, bl;
                wmma::load_matrix_sync(bh, shi + gg * 16 * LDB + kt * 16, LDB);
                wmma::load_matrix_sync(bl, slo + gg * 16 * LDB + kt * 16, LDB);
                wmma::mma_sync(acc[gg], ahi, bh, acc[gg]);
                wmma::mma_sync(acc[gg], alo, bh, acc[gg]);
                wmma::mma_sync(acc[gg], ahi, bl, acc[gg]);
            }
            __syncwarp();
        }
        reduce3(stage, rb * 3, ks, acc);
        for (int e = tid; e < 64 * 16; e += NTHREADS) {
            int row = e >> 4, c = e & 15, rb2 = row >> 4, rr = row & 15;
            int gc = cidx * 16 + c;
            const float* st = stage + rb2 * 3 * TILE_F;
            float* dst = &g_gi0[((size_t)t * BB + row) * G3];
            dst[gc]        = st[rr * SLD + c]              + bih[gc];
            dst[512 + gc]  = st[TILE_F + rr * SLD + c]     + bih[512 + gc];
            dst[1024 + gc] = st[2 * TILE_F + rr * SLD + c] + bih[1024 + gc];
        }
        __syncthreads();
    }
}

// ---------------- main: 64 L0 (6-way ksplit) + 64 L1; group-local counters ---
extern "C" __global__ void __launch_bounds__(NTHREADS, 1)
gru_main(const float* __restrict__ Wih, const float* __restrict__ Whh,
         const float* __restrict__ bih, const float* __restrict__ bhh,
         float* __restrict__ out) {
    extern __shared__ __half smem[];
    const int bid = blockIdx.x, tid = threadIdx.x;
    const int wid = tid >> 5, lane = tid & 31;
    const bool L0 = (bid < 64);

    __half *sWih_hi = nullptr, *sWih_lo = nullptr, *sWhh_hi, *sWhh_lo;
    float* stage;
    int cidx, grp, b0;

    if (L0) {
        grp = bid >> 5; cidx = bid & 31; b0 = grp * 32;
        sWhh_hi = smem; sWhh_lo = smem + 48 * LDB;
        stage = (float*)(smem + 2 * 48 * LDB);        // 36 tiles
        load_weights(Whh, sWhh_hi, sWhh_lo, cidx);
    } else {
        int r = bid - 64;
        grp = r >> 5; cidx = r & 31; b0 = grp * 32;
        sWih_hi = smem;                sWih_lo = smem + 48 * LDB;
        sWhh_hi = smem + 2 * 48 * LDB; sWhh_lo = smem + 3 * 48 * LDB;
        stage = (float*)(smem + 4 * 48 * LDB);        // 12 tiles
        load_weights(Wih + (size_t)G3 * KK, sWih_hi, sWih_lo, cidx);
        load_weights(Whh + (size_t)G3 * KK, sWhh_hi, sWhh_lo, cidx);
    }
    __syncthreads();

    int srcid, rb, ks, k0, k1;
    if (L0) {
        srcid = 1; rb = wid / 6; ks = wid % 6;
        k0 = (ks < 2) ? ks * 6 : 12 + (ks - 2) * 5;
        k1 = k0 + ((ks < 2) ? 6 : 5);
    } else {
        srcid = wid / 6; rb = (wid % 6) / 3; ks = wid % 3;
        k0 = ks * 11; k1 = (ks == 2) ? 32 : k0 + 11;
    }
    const int tilebase = L0 ? 0 : ((srcid * 2 + rb) * 3);
    const int layer = L0 ? 0 : 1;
    const float* bihL = bih + layer * G3;
    const float* bhhL = bhh + layer * G3;

    // ---- epilogue caches: biases + exact h_prev in registers ----
    float cbiR[2], cbiZ[2], cbiN[2], cbhR[2], cbhZ[2], cbhN[2], hp_reg[2];
    int nelem = 0;
#pragma unroll
    for (int q = 0; q < 2; q++) {
        int e = tid + q * NTHREADS;
        if (e >= 32 * 16) break;
        int row = e >> 4, c = e & 15;
        int gc = cidx * 16 + c;
        int hidx = (b0 + row) * KK + gc;
        cbiR[q] = L0 ? 0.f : bihL[gc];
        cbiZ[q] = L0 ? 0.f : bihL[512 + gc];
        cbiN[q] = L0 ? 0.f : bihL[1024 + gc];
        cbhR[q] = bhhL[gc];
        cbhZ[q] = bhhL[512 + gc];
        cbhN[q] = bhhL[1024 + gc];
        hp_reg[q] = __half2float(g_h_hi[layer][1][hidx]) +
                    __half2float(g_h_lo[layer][1][hidx]);
        nelem++;
    }

    for (int t = 0; t < TT; t++) {
        // gi0 prefetch (L0): immutable, overlaps wait + GEMM
        float pgi[6];
        if (L0) {
#pragma unroll
            for (int q = 0; q < 2; q++) {
                int e = tid + q * NTHREADS;
                if (e >= 32 * 16) break;
                int row = e >> 4, c = e & 15;
                const float* gi = &g_gi0[((size_t)t * BB + b0 + row) * G3] + cidx * 16 + c;
                pgi[q * 3 + 0] = gi[0];
                pgi[q * 3 + 1] = gi[512];
                pgi[q * 3 + 2] = gi[1024];
            }
        }

        // ---- r10 spin structure, group-local counters ----
        if (lane == 0) {
            if (L0) {
                spin_ge(&g_c0g[grp][0], (unsigned)(32 * t));
                if (t >= 1) spin_ge(&g_c1g[grp][0], (unsigned)(32 * (t - 1)));
            } else if (srcid == 0) {
                spin_ge(&g_c0g[grp][0], (unsigned)(32 * (t + 1)));  // need h0(t)
            } else {
                spin_ge(&g_c1g[grp][0], (unsigned)(32 * t));        // need h1(t-1)
            }
            fence_gpu();
        }
        __syncwarp();

        const __half *Ahi, *Alo;
        if (L0) {
            int pv = (t + 1) & 1;
            Ahi = &g_h_hi[0][pv][b0 * KK] + rb * 16 * KK;
            Alo = &g_h_lo[0][pv][b0 * KK] + rb * 16 * KK;
        } else if (srcid == 0) {
            int p = t & 1;
            Ahi = &g_h_hi[0][p][b0 * KK] + rb * 16 * KK;
            Alo = &g_h_lo[0][p][b0 * KK] + rb * 16 * KK;
        } else {
            int pv = (t + 1) & 1;
            Ahi = &g_h_hi[1][pv][b0 * KK] + rb * 16 * KK;
            Alo = &g_h_lo[1][pv][b0 * KK] + rb * 16 * KK;
        }
        const __half* Bh = (srcid == 0) ? sWih_hi : sWhh_hi;
        const __half* Bl = (srcid == 0) ? sWih_lo : sWhh_lo;

        AccFrag acc[3];
#pragma unroll
        for (int gg = 0; gg < 3; gg++) wmma::fill_fragment(acc[gg], 0.0f);
        gemm3(Ahi, Alo, KK, Bh, Bl, k0, k1, acc);

        if (L0) {
#pragma unroll
            for (int gg = 0; gg < 3; gg++)
                wmma::store_matrix_sync(stage + (wid * 3 + gg) * TILE_F, acc[gg],
                                        SLD, wmma::mem_row_major);
            __syncthreads();
        } else {
            reduce3(stage, tilebase, ks, acc);
        }

#pragma unroll
        for (int q = 0; q < 2; q++) {
            if (q >= nelem) break;
            int e = tid + q * NTHREADS;
            int row = e >> 4, c = e & 15, rb2 = row >> 4, rr = row & 15;
            int gc = cidx * 16 + c;
            float giR, giZ, giN, ghR, ghZ, ghN;
            if (L0) {
                giR = pgi[q * 3 + 0]; giZ = pgi[q * 3 + 1]; giN = pgi[q * 3 + 2];
                ghR = 0.f; ghZ = 0.f; ghN = 0.f;
                const int off = rr * SLD + c;
#pragma unroll
                for (int s = 0; s < 6; s++) {
                    const float* tp = stage + ((rb2 * 6 + s) * 3) * TILE_F + off;
                    ghR += tp[0];
                    ghZ += tp[TILE_F];
                    ghN += tp[2 * TILE_F];
                }
            } else {
                const float* sg = stage + rb2 * 3 * TILE_F;
                const float* sh = stage + (2 + rb2) * 3 * TILE_F;
                giR = sg[rr * SLD + c]              + cbiR[q];
                giZ = sg[TILE_F + rr * SLD + c]     + cbiZ[q];
                giN = sg[2 * TILE_F + rr * SLD + c] + cbiN[q];
                ghR = sh[rr * SLD + c];
                ghZ = sh[TILE_F + rr * SLD + c];
                ghN = sh[2 * TILE_F + rr * SLD + c];
            }
            float r = 1.0f / (1.0f + expf(-(giR + ghR + cbhR[q])));
            float z = 1.0f / (1.0f + expf(-(giZ + ghZ + cbhZ[q])));
            float n = tanhf(giN + r * (ghN + cbhN[q]));

            int hidx = (b0 + row) * KK + gc;
            float hn = (1.0f - z) * n + z * hp_reg[q];
            hp_reg[q] = hn;

            int pc = t & 1;
            __half hh = __float2half_rn(hn);
            g_h_hi[layer][pc][hidx] = hh;
            g_h_lo[layer][pc][hidx] = __float2half_rn(hn - __half2float(hh));

            if (!L0)
                out[((size_t)(b0 + row) * TT + t) * KK + gc] = hn;
            if (t == TT - 1)
                out[(size_t)BB * TT * KK + (size_t)layer * BB * KK + hidx] = hn;
        }
        __syncthreads();
        if (tid == 0) {
            fence_gpu();
            if (L0) atomicAdd(&g_c0g[grp][0], 1u);
            else    atomicAdd(&g_c1g[grp][0], 1u);
        }
    }
}

extern "C" void kernel_launch(void* const* d_in, const int* in_sizes, int n_in,
                              void* d_out, int out_size) {
    const float* x   = (const float*)d_in[0];
    const float* enc = (const float*)d_in[1];
    const float* Wih = (const float*)d_in[2];
    const float* Whh = (const float*)d_in[3];
    const float* bih = (const float*)d_in[4];
    const float* bhh = (const float*)d_in[5];
    float* out = (float*)d_out;
    (void)in_sizes; (void)n_in; (void)out_size;

    size_t smem_main = (size_t)4 * 48 * LDB * 2 + (size_t)12 * TILE_F * 4;
    size_t smem_bulk = (size_t)2 * 48 * LDB * 2 + (size_t)12 * TILE_F * 4
                     + (size_t)12 * 2 * 16 * ABUF_LD * 2;
    cudaFuncSetAttribute(gru_main, cudaFuncAttributeMaxDynamicSharedMemorySize,
                         (int)smem_main);
    cudaFuncSetAttribute(gru_bulk, cudaFuncAttributeMaxDynamicSharedMemorySize,
                         (int)smem_bulk);

    gru_bulk<<<512, NTHREADS, smem_bulk>>>(x, enc, Wih, bih);
    gru_main<<<128, NTHREADS, smem_main>>>(Wih, Whh, bih, bhh, out);
}